// round 17
// baseline (speedup 1.0000x reference)
#include <cuda_runtime.h>
#include <cuda_bf16.h>
#include <cuda_pipeline_primitives.h>
#include <mma.h>

using namespace nvcuda;

#define NSEQ 2048
#define CDIM 1024
#define HEADS 16
#define HD 64
#define BATCH 4
#define BH (BATCH*HEADS)
#define MTOT (BATCH*NSEQ)
#define KC 32
#define PADK 40
#define KV_LD 80
#define SF_LD 68
#define KVB 5120
#define BUFH 20480
#define W_LO_OFF 6291456

__device__ __nv_bfloat16 g_qh[(size_t)BH*NSEQ*HD];
__device__ __nv_bfloat16 g_ql[(size_t)BH*NSEQ*HD];
__device__ __nv_bfloat16 g_kh[(size_t)BH*NSEQ*HD];
__device__ __nv_bfloat16 g_kl[(size_t)BH*NSEQ*HD];
__device__ __nv_bfloat16 g_vh[(size_t)BH*NSEQ*HD];
__device__ __nv_bfloat16 g_vl[(size_t)BH*NSEQ*HD];
// 32 MiB arena, time-shared: [0,12MiB) qkv_w hi/lo split (live until gemm<0> done),
// then the whole 32 MiB is the attention output (fp32), read by gemm<1>.
// Total statics match the Round-12 footprint exactly (one 128 MiB slab).
__device__ __align__(16) char g_arena[33554432];
__device__ float g_msum[BATCH];

// split fp32 pair into hi/lo bf16x2
__device__ __forceinline__ void split2(float a, float b, __nv_bfloat162& hi, __nv_bfloat162& lo) {
    __nv_bfloat16 ha = __float2bfloat16_rn(a);
    __nv_bfloat16 hb = __float2bfloat16_rn(b);
    hi = __halves2bfloat162(ha, hb);
    lo = __halves2bfloat162(__float2bfloat16_rn(a - __bfloat162float(ha)),
                            __float2bfloat16_rn(b - __bfloat162float(hb)));
}

// FMA-pipe exp (no MUFU)
__device__ __forceinline__ float fexp(float s) {
    s = fminf(fmaxf(s, -60.f), 60.f);
    float y = s * 1.4426950408889634f;
    float n = rintf(y);
    float f = y - n;
    float p = 1.3333558146428443e-3f;
    p = fmaf(p, f, 9.6181291076284772e-3f);
    p = fmaf(p, f, 5.5504108664821580e-2f);
    p = fmaf(p, f, 2.4022650695910072e-1f);
    p = fmaf(p, f, 6.9314718055994531e-1f);
    p = fmaf(p, f, 1.0f);
    int e = (int)n;
    return p * __int_as_float((e + 127) << 23);
}

__global__ void masksum_kernel(const float* __restrict__ mWin) {
    int b = blockIdx.x;
    float s = 0.f;
    for (int i = threadIdx.x; i < NSEQ; i += blockDim.x) {
        float v = mWin[b*NSEQ + i];
        s += v*v;
    }
    for (int o = 16; o; o >>= 1) s += __shfl_xor_sync(~0u, s, o);
    __shared__ float sm[8];
    if ((threadIdx.x & 31) == 0) sm[threadIdx.x >> 5] = s;
    __syncthreads();
    if (threadIdx.x < 8) {
        float t = sm[threadIdx.x];
        for (int o = 4; o; o >>= 1) t += __shfl_xor_sync(0xffu, t, o);
        if (threadIdx.x == 0) g_msum[b] = t;
    }
}

// elementwise fp32 -> bf16 hi/lo pre-split (for qkv_w, into the arena head)
__global__ void split_kernel(const float* __restrict__ src, int n) {
    __nv_bfloat16* dh = (__nv_bfloat16*)g_arena;
    __nv_bfloat16* dl = (__nv_bfloat16*)(g_arena + W_LO_OFF);
    int i = (blockIdx.x*blockDim.x + threadIdx.x)*4;
    if (i < n) {
        float4 v = *(const float4*)(src + i);
        __nv_bfloat162 h0, l0, h1, l1;
        split2(v.x, v.y, h0, l0);
        split2(v.z, v.w, h1, l1);
        *(__nv_bfloat162*)&dh[i] = h0;
        *(__nv_bfloat162*)&dh[i+2] = h1;
        *(__nv_bfloat162*)&dl[i] = l0;
        *(__nv_bfloat162*)&dl[i+2] = l1;
    }
}

typedef wmma::fragment<wmma::matrix_a, 16, 16, 16, __nv_bfloat16, wmma::row_major> FA;
typedef wmma::fragment<wmma::matrix_b, 16, 16, 16, __nv_bfloat16, wmma::col_major> FBc;
typedef wmma::fragment<wmma::matrix_b, 16, 16, 16, __nv_bfloat16, wmma::row_major> FBr;
typedef wmma::fragment<wmma::accumulator, 16, 16, 16, float> FC;

// NT gemm, bf16-split via WMMA, register-prefetch one k-chunk ahead.
// MODE 0: A = x fp32 (in-kernel split); B = qkv_w PRE-SPLIT from arena.
//         epilogue: mask/scale, scatter hi/lo to g_q/k/v.
// MODE 1: A = attention output fp32 (arena, in-kernel split); B = proj_w fp32
//         (in-kernel split). epilogue: bias, write d_out.
template <int MODE>
__global__ __launch_bounds__(256, 1) void wmma_gemm(
    const float* __restrict__ Ain, const float* __restrict__ Bin, int K,
    const float* __restrict__ mask, const float* __restrict__ bias, float* __restrict__ out)
{
    __shared__ __align__(16) __nv_bfloat16 Ah[128*PADK];
    __shared__ __align__(16) __nv_bfloat16 Al[128*PADK];
    __shared__ __align__(16) __nv_bfloat16 Bh2[128*PADK];
    __shared__ __align__(16) __nv_bfloat16 Bl2[128*PADK];

    const float* A = (MODE == 1) ? (const float*)g_arena : Ain;
    const int bm = blockIdx.y*128, bn = blockIdx.x*128;
    const int tid = threadIdx.x, lane = tid & 31, wid = tid >> 5;
    const int wm = (wid >> 2)*64;
    const int wn = (wid & 3)*32;
    const int lr = tid >> 3, lc = (tid & 7)*4;

    FC acc[4][2];
    for (int mi = 0; mi < 4; mi++)
        for (int ni = 0; ni < 2; ni++)
            wmma::fill_fragment(acc[mi][ni], 0.f);

    const float* Abase = A + (size_t)(bm + lr)*K + lc;
    const float* Bbase = (MODE == 1) ? (Bin + (size_t)(bn + lr)*K + lc) : (const float*)0;
    const __nv_bfloat16* WhBase = (const __nv_bfloat16*)g_arena + (size_t)(bn + lr)*K + lc;
    const __nv_bfloat16* WlBase = (const __nv_bfloat16*)(g_arena + W_LO_OFF) + (size_t)(bn + lr)*K + lc;

    float4 av[4];
    float4 bv[4];
    uint2 bvh[4], bvl[4];
    #pragma unroll
    for (int j = 0; j < 4; j++) {
        av[j] = *(const float4*)(Abase + (size_t)(j*32)*K);
        if (MODE == 1) {
            bv[j] = *(const float4*)(Bbase + (size_t)(j*32)*K);
        } else {
            bvh[j] = *(const uint2*)(WhBase + (size_t)(j*32)*K);
            bvl[j] = *(const uint2*)(WlBase + (size_t)(j*32)*K);
        }
    }

    for (int k0 = 0; k0 < K; k0 += KC) {
        __syncthreads();
        #pragma unroll
        for (int j = 0; j < 4; j++) {
            int base = (lr + j*32)*PADK + lc;
            __nv_bfloat162 h0, l0, h1, l1;
            split2(av[j].x, av[j].y, h0, l0);
            split2(av[j].z, av[j].w, h1, l1);
            *(__nv_bfloat162*)&Ah[base] = h0;
            *(__nv_bfloat162*)&Ah[base+2] = h1;
            *(__nv_bfloat162*)&Al[base] = l0;
            *(__nv_bfloat162*)&Al[base+2] = l1;
            if (MODE == 1) {
                split2(bv[j].x, bv[j].y, h0, l0);
                split2(bv[j].z, bv[j].w, h1, l1);
                *(__nv_bfloat162*)&Bh2[base] = h0;
                *(__nv_bfloat162*)&Bh2[base+2] = h1;
                *(__nv_bfloat162*)&Bl2[base] = l0;
                *(__nv_bfloat162*)&Bl2[base+2] = l1;
            } else {
                *(uint2*)&Bh2[base] = bvh[j];
                *(uint2*)&Bl2[base] = bvl[j];
            }
        }
        __syncthreads();
        // prefetch next chunk while the tensor cores chew on this one
        if (k0 + KC < K) {
            #pragma unroll
            for (int j = 0; j < 4; j++) {
                av[j] = *(const float4*)(Abase + (size_t)(j*32)*K + k0 + KC);
                if (MODE == 1) {
                    bv[j] = *(const float4*)(Bbase + (size_t)(j*32)*K + k0 + KC);
                } else {
                    bvh[j] = *(const uint2*)(WhBase + (size_t)(j*32)*K + k0 + KC);
                    bvl[j] = *(const uint2*)(WlBase + (size_t)(j*32)*K + k0 + KC);
                }
            }
        }
        #pragma unroll
        for (int ks = 0; ks < KC; ks += 16) {
            FA fah[4], fal[4];
            FBc fbh[2], fbl[2];
            #pragma unroll
            for (int mi = 0; mi < 4; mi++) {
                int ao = (wm + mi*16)*PADK + ks;
                wmma::load_matrix_sync(fah[mi], &Ah[ao], PADK);
                wmma::load_matrix_sync(fal[mi], &Al[ao], PADK);
            }
            #pragma unroll
            for (int ni = 0; ni < 2; ni++) {
                int bo = (wn + ni*16)*PADK + ks;
                wmma::load_matrix_sync(fbh[ni], &Bh2[bo], PADK);
                wmma::load_matrix_sync(fbl[ni], &Bl2[bo], PADK);
            }
            #pragma unroll
            for (int mi = 0; mi < 4; mi++) {
                #pragma unroll
                for (int ni = 0; ni < 2; ni++) {
                    wmma::mma_sync(acc[mi][ni], fah[mi], fbh[ni], acc[mi][ni]);
                    wmma::mma_sync(acc[mi][ni], fah[mi], fbl[ni], acc[mi][ni]);
                    wmma::mma_sync(acc[mi][ni], fal[mi], fbh[ni], acc[mi][ni]);
                }
            }
        }
    }

    __syncthreads();
    float* stage = (float*)Ah;
    float* ws = stage + wid*256;
    const int srow = lane >> 1;
    const int scol = (lane & 1)*8;
    for (int mi = 0; mi < 4; mi++) {
        for (int ni = 0; ni < 2; ni++) {
            wmma::store_matrix_sync(ws, acc[mi][ni], 16, wmma::mem_row_major);
            __syncwarp();
            int r = bm + wm + mi*16 + srow;
            int col = bn + wn + ni*16 + scol;
            float4 p0 = *(float4*)&ws[srow*16 + scol];
            float4 p1 = *(float4*)&ws[srow*16 + scol + 4];
            if (MODE == 0) {
                int which = col >> 10, cc = col & 1023;
                float f = mask[r]*((which == 0) ? 0.125f : 1.f);
                __nv_bfloat16* dh = (which == 0) ? g_qh : ((which == 1) ? g_kh : g_vh);
                __nv_bfloat16* dl = (which == 0) ? g_ql : ((which == 1) ? g_kl : g_vl);
                int b = r >> 11, nq = r & 2047, h2 = cc >> 6, d = cc & 63;
                size_t off = ((size_t)(b*HEADS + h2)*NSEQ + nq)*HD + d;
                float vals[8];
                vals[0] = p0.x; vals[1] = p0.y; vals[2] = p0.z; vals[3] = p0.w;
                vals[4] = p1.x; vals[5] = p1.y; vals[6] = p1.z; vals[7] = p1.w;
                __nv_bfloat16 hh[8], ll[8];
                #pragma unroll
                for (int j = 0; j < 8; j++) {
                    float v = vals[j]*f;
                    __nv_bfloat16 hv = __float2bfloat16_rn(v);
                    hh[j] = hv;
                    ll[j] = __float2bfloat16_rn(v - __bfloat162float(hv));
                }
                *(uint4*)&dh[off] = *(uint4*)hh;
                *(uint4*)&dl[off] = *(uint4*)ll;
            } else {
                float4 b0 = *(const float4*)&bias[col];
                float4 b1 = *(const float4*)&bias[col+4];
                float* dp = out + (size_t)r*CDIM + col;
                *(float4*)dp = make_float4(p0.x+b0.x, p0.y+b0.y, p0.z+b0.z, p0.w+b0.w);
                *(float4*)(dp+4) = make_float4(p1.x+b1.x, p1.y+b1.y, p1.z+b1.z, p1.w+b1.w);
            }
            __syncwarp();
        }
    }
}

// prefetch one 64-row k-tile (KH,KL,VH,VL) into a smem buffer via cp.async
__device__ __forceinline__ void prefetch_tile(int tid, size_t base, int kt, __nv_bfloat16* buf) {
    #pragma unroll
    for (int t = 0; t < 8; t++) {
        int c = tid + t*256;
        int arr = c >> 9, rem = c & 511;
        int row = rem >> 3, seg = rem & 7;
        const __nv_bfloat16* src;
        if (arr == 0) src = g_kh;
        else if (arr == 1) src = g_kl;
        else if (arr == 2) src = g_vh;
        else src = g_vl;
        __pipeline_memcpy_async(buf + arr*KVB + row*KV_LD + seg*8,
                                src + base + (size_t)(kt + row)*HD + seg*8, 16);
    }
}

// tensor-core attention: 256 thr / 8 warps, 128 q-rows per CTA,
// double-buffered cp.async K/V, warp-local S/exp/P, fp32 output into the arena.
__global__ __launch_bounds__(256, 1) void attn_mma(const float* __restrict__ mWin) {
    extern __shared__ char smraw[];
    __nv_bfloat16* KV = (__nv_bfloat16*)smraw;
    __nv_bfloat16* PHs = KV + 2*BUFH;
    __nv_bfloat16* PLs = PHs + 128*KV_LD;
    float* SF = (float*)(PLs + 128*KV_LD);
    float* DENs = SF + 128*SF_LD;

    const int tid = threadIdx.x, w = tid >> 5;
    const int bh = blockIdx.y, b = bh >> 4, h = bh & 15;
    const int q0 = blockIdx.x*128;
    const size_t base = (size_t)bh*NSEQ*HD;

    FA qfh[4], qfl[4];
    {
        const __nv_bfloat16* qp = g_qh + base + (size_t)(q0 + w*16)*HD;
        const __nv_bfloat16* qp2 = g_ql + base + (size_t)(q0 + w*16)*HD;
        #pragma unroll
        for (int kk = 0; kk < 4; kk++) {
            wmma::load_matrix_sync(qfh[kk], qp + kk*16, HD);
            wmma::load_matrix_sync(qfl[kk], qp2 + kk*16, HD);
        }
    }

    FC o[4];
    #pragma unroll
    for (int i = 0; i < 4; i++) wmma::fill_fragment(o[i], 0.f);
    float den = 0.f;
    const int erow = tid >> 1, ecol = (tid & 1)*32;

    prefetch_tile(tid, base, 0, KV);
    __pipeline_commit();

    for (int it = 0; it < 32; it++) {
        __syncthreads();
        if (it + 1 < 32) prefetch_tile(tid, base, (it+1)*64, KV + ((it+1)&1)*BUFH);
        __pipeline_commit();
        __pipeline_wait_prior(1);
        __syncthreads();

        __nv_bfloat16* KHb = KV + (it&1)*BUFH;
        __nv_bfloat16* KLb = KHb + KVB;
        __nv_bfloat16* VHb = KHb + 2*KVB;
        __nv_bfloat16* VLb = KHb + 3*KVB;

        #pragma unroll
        for (int n = 0; n < 4; n++) {
            FC s;
            wmma::fill_fragment(s, 0.f);
            #pragma unroll
            for (int kk = 0; kk < 4; kk++) {
                FBc kbh, kbl;
                wmma::load_matrix_sync(kbh, KHb + n*16*KV_LD + kk*16, KV_LD);
                wmma::load_matrix_sync(kbl, KLb + n*16*KV_LD + kk*16, KV_LD);
                wmma::mma_sync(s, qfh[kk], kbh, s);
                wmma::mma_sync(s, qfh[kk], kbl, s);
                wmma::mma_sync(s, qfl[kk], kbh, s);
            }
            wmma::store_matrix_sync(SF + w*16*SF_LD + n*16, s, SF_LD, wmma::mem_row_major);
        }
        __syncwarp();

        #pragma unroll
        for (int j = 0; j < 32; j += 2) {
            float2 sv = *(float2*)&SF[erow*SF_LD + ecol + j];
            float p0 = fexp(sv.x);
            float p1 = fexp(sv.y);
            den += p0 + p1;
            __nv_bfloat162 hi, lo;
            split2(p0, p1, hi, lo);
            *(__nv_bfloat162*)&PHs[erow*KV_LD + ecol + j] = hi;
            *(__nv_bfloat162*)&PLs[erow*KV_LD + ecol + j] = lo;
        }
        __syncwarp();

        FA pa[4], pb[4];
        #pragma unroll
        for (int kk = 0; kk < 4; kk++) {
            wmma::load_matrix_sync(pa[kk], PHs + w*16*KV_LD + kk*16, KV_LD);
            wmma::load_matrix_sync(pb[kk], PLs + w*16*KV_LD + kk*16, KV_LD);
        }
        #pragma unroll
        for (int nd = 0; nd < 4; nd++) {
            #pragma unroll
            for (int kk = 0; kk < 4; kk++) {
                FBr vbh, vbl;
                wmma::load_matrix_sync(vbh, VHb + kk*16*KV_LD + nd*16, KV_LD);
                wmma::load_matrix_sync(vbl, VLb + kk*16*KV_LD + nd*16, KV_LD);
                wmma::mma_sync(o[nd], pa[kk], vbh, o[nd]);
                wmma::mma_sync(o[nd], pa[kk], vbl, o[nd]);
                wmma::mma_sync(o[nd], pb[kk], vbh, o[nd]);
            }
        }
    }

    DENs[tid] = den;
    #pragma unroll
    for (int nd = 0; nd < 4; nd++)
        wmma::store_matrix_sync(SF + w*16*SF_LD + nd*16, o[nd], SF_LD, wmma::mem_row_major);
    __syncthreads();
    {
        int nq = q0 + erow;
        float dsum = DENs[erow*2] + DENs[erow*2+1];
        float mk = mWin[b*NSEQ + nq];
        float sc = 1.f/(dsum*(mk*g_msum[b] + 1e-6f));
        float* op = (float*)g_arena + (size_t)(b*NSEQ + nq)*CDIM + h*HD + ecol;
        #pragma unroll
        for (int j = 0; j < 32; j += 4) {
            float4 v = *(float4*)&SF[erow*SF_LD + ecol + j];
            *(float4*)&op[j] = make_float4(v.x*sc, v.y*sc, v.z*sc, v.w*sc);
        }
    }
}

extern "C" void kernel_launch(void* const* d_in, const int* in_sizes, int n_in,
                              void* d_out, int out_size) {
    const float* x = (const float*)d_in[0];
    const float* mWin = (const float*)d_in[1];
    const float* qkv_w = (const float*)d_in[2];
    const float* proj_w = (const float*)d_in[3];
    const float* proj_b = (const float*)d_in[4];
    float* out = (float*)d_out;

    const int attn_smem = (2*BUFH + 2*128*KV_LD)*2 + 128*SF_LD*4 + 256*4;
    cudaFuncSetAttribute(attn_mma, cudaFuncAttributeMaxDynamicSharedMemorySize, attn_smem);

    split_kernel<<<3*CDIM*CDIM/1024, 256>>>(qkv_w, 3*CDIM*CDIM);
    masksum_kernel<<<BATCH, 256>>>(mWin);

    wmma_gemm<0><<<dim3(3*CDIM/128, MTOT/128), 256>>>(x, nullptr, CDIM, mWin, nullptr, nullptr);
    attn_mma<<<dim3(NSEQ/128, BH), 256, attn_smem>>>(mWin);
    wmma_gemm<1><<<dim3(CDIM/128, MTOT/128), 256>>>(nullptr, proj_w, CDIM, nullptr, proj_b, out);
}